// round 2
// baseline (speedup 1.0000x reference)
#include <cuda_runtime.h>

// RotaryEmbedding: x (4,16,8192,64) fp32. Rotate first 4 pairs (elems 0..7)
// of each 64-float row; copy the remaining 56 floats unchanged.
//
// R1: 4 float4/thread (block-strided, stride 256 == 0 mod 16 so all 4 chunks
// of one thread share col4 -> no intra-thread divergence), plus rotation
// coefficients precomputed by a 1-thread kernel into a __device__ global.
// Pure HBM-bound streaming: 256 MiB traffic.

__device__ float g_cs[8];   // [c0,s0,c1,s1,c2,s2,c3,s3]

__global__ void rope_coeffs(const float* __restrict__ dparam,
                            const float* __restrict__ thetas)
{
    if (threadIdx.x == 0) {
        // direction = sigmoid(d)*2 - 1 = tanh(d/2)
        float d = tanhf(0.5f * dparam[0]);
        #pragma unroll
        for (int p = 0; p < 4; p++) {
            float s, c;
            sincosf(d * thetas[p], &s, &c);
            g_cs[2 * p]     = c;
            g_cs[2 * p + 1] = s;
        }
    }
}

__global__ __launch_bounds__(256) void rope4_kernel(
    const float4* __restrict__ x,
    float4*       __restrict__ out,
    int n4)
{
    int base = blockIdx.x * (256 * 4) + threadIdx.x;

    float4 v[4];
    #pragma unroll
    for (int k = 0; k < 4; k++) {
        int i = base + k * 256;
        v[k] = (i < n4) ? x[i] : make_float4(0.f, 0.f, 0.f, 0.f);
    }

    int col4 = base & 15;           // 256-stride preserves col4 across k
    if (col4 < 2) {
        int p = col4 * 2;           // first rotating pair in this chunk
        float c0 = g_cs[2 * p],     s0 = g_cs[2 * p + 1];
        float c1 = g_cs[2 * p + 2], s1 = g_cs[2 * p + 3];
        #pragma unroll
        for (int k = 0; k < 4; k++) {
            float xi0 = v[k].x, xj0 = v[k].y;
            float xi1 = v[k].z, xj1 = v[k].w;
            v[k].x =  xi0 * c0 + xj0 * s0;
            v[k].y = -xi0 * s0 + xj0 * c0;
            v[k].z =  xi1 * c1 + xj1 * s1;
            v[k].w = -xi1 * s1 + xj1 * c1;
        }
    }

    #pragma unroll
    for (int k = 0; k < 4; k++) {
        int i = base + k * 256;
        if (i < n4) out[i] = v[k];
    }
}

extern "C" void kernel_launch(void* const* d_in, const int* in_sizes, int n_in,
                              void* d_out, int out_size)
{
    const float4* x      = (const float4*)d_in[0];
    const float*  dparam = (const float*)d_in[1];
    const float*  thetas = (const float*)d_in[2];
    float4*       out    = (float4*)d_out;

    int n4 = in_sizes[0] / 4;                   // 8,388,608 float4 chunks
    rope_coeffs<<<1, 32>>>(dparam, thetas);
    int blocks = (n4 + 256 * 4 - 1) / (256 * 4);  // 8192
    rope4_kernel<<<blocks, 256>>>(x, out, n4);
}

// round 3
// speedup vs baseline: 1.0816x; 1.0816x over previous
#include <cuda_runtime.h>

// RotaryEmbedding: x (4,16,8192,64) fp32. Rotate first 4 pairs (elems 0..7)
// of each 64-float row; copy the remaining 56 floats unchanged.
//
// R2: single kernel (the separate coeff kernel cost ~10us of graph overhead),
// 8 float4/thread block-strided (stride 256 == 0 mod 16, so all 8 chunks of a
// thread share col4 -> one coefficient computation, no divergence across k).
// Rotating threads (col4 < 2, i.e. 4 lanes/warp) compute tanh + 2 sincos
// inline once. Pure HBM streaming: 256 MiB traffic.

#define CHUNKS 8
#define TPB 256

__global__ __launch_bounds__(TPB) void rope8_kernel(
    const float4* __restrict__ x,
    const float*  __restrict__ dparam,
    const float*  __restrict__ thetas,
    float4*       __restrict__ out,
    int n4)
{
    int base = blockIdx.x * (TPB * CHUNKS) + threadIdx.x;

    float4 v[CHUNKS];
    #pragma unroll
    for (int k = 0; k < CHUNKS; k++) {
        int i = base + k * TPB;
        if (i < n4) v[k] = x[i];
    }

    int col4 = base & 15;           // TPB-stride preserves col4 across k
    if (col4 < 2) {
        // direction = sigmoid(d)*2 - 1 = tanh(d/2)
        float d = tanhf(0.5f * dparam[0]);
        int p = col4 * 2;           // first rotating pair in this chunk
        float s0, c0, s1, c1;
        sincosf(d * thetas[p],     &s0, &c0);
        sincosf(d * thetas[p + 1], &s1, &c1);
        #pragma unroll
        for (int k = 0; k < CHUNKS; k++) {
            float xi0 = v[k].x, xj0 = v[k].y;
            float xi1 = v[k].z, xj1 = v[k].w;
            v[k].x =  xi0 * c0 + xj0 * s0;
            v[k].y = -xi0 * s0 + xj0 * c0;
            v[k].z =  xi1 * c1 + xj1 * s1;
            v[k].w = -xi1 * s1 + xj1 * c1;
        }
    }

    #pragma unroll
    for (int k = 0; k < CHUNKS; k++) {
        int i = base + k * TPB;
        if (i < n4) out[i] = v[k];
    }
}

extern "C" void kernel_launch(void* const* d_in, const int* in_sizes, int n_in,
                              void* d_out, int out_size)
{
    const float4* x      = (const float4*)d_in[0];
    const float*  dparam = (const float*)d_in[1];
    const float*  thetas = (const float*)d_in[2];
    float4*       out    = (float4*)d_out;

    int n4 = in_sizes[0] / 4;                         // 8,388,608 float4 chunks
    int blocks = (n4 + TPB * CHUNKS - 1) / (TPB * CHUNKS);  // 4096
    rope8_kernel<<<blocks, TPB>>>(x, dparam, thetas, out, n4);
}

// round 4
// speedup vs baseline: 1.0824x; 1.0007x over previous
#include <cuda_runtime.h>

// RotaryEmbedding: x (4,16,8192,64) fp32. Rotate first 4 pairs (elems 0..7)
// of each 64-float row; copy the remaining 56 floats unchanged.
//
// R3: exact-cover kernel (no bounds predicates; n4 divides TPB*CHUNKS for
// this shape, guarded fallback otherwise), streaming cache hints
// (__ldcs/__stcs: read-once/write-once), 8 float4/thread block-strided.
// Stride 256 == 0 mod 16 -> col4 invariant across chunks, one coefficient
// computation for rotating lanes (4 of 32 per warp). 256 MiB HBM stream.

#define CHUNKS 8
#define TPB 256

__device__ __forceinline__ void rope_math(float4 v[CHUNKS], int col4,
                                          const float* __restrict__ dparam,
                                          const float* __restrict__ thetas)
{
    if (col4 < 2) {
        // direction = sigmoid(d)*2 - 1 = tanh(d/2)
        float d = tanhf(0.5f * dparam[0]);
        int p = col4 * 2;
        float s0, c0, s1, c1;
        sincosf(d * thetas[p],     &s0, &c0);
        sincosf(d * thetas[p + 1], &s1, &c1);
        #pragma unroll
        for (int k = 0; k < CHUNKS; k++) {
            float xi0 = v[k].x, xj0 = v[k].y;
            float xi1 = v[k].z, xj1 = v[k].w;
            v[k].x =  xi0 * c0 + xj0 * s0;
            v[k].y = -xi0 * s0 + xj0 * c0;
            v[k].z =  xi1 * c1 + xj1 * s1;
            v[k].w = -xi1 * s1 + xj1 * c1;
        }
    }
}

// Fast path: grid covers n4 exactly, no guards.
__global__ __launch_bounds__(TPB) void rope8_exact(
    const float4* __restrict__ x,
    const float*  __restrict__ dparam,
    const float*  __restrict__ thetas,
    float4*       __restrict__ out)
{
    int base = blockIdx.x * (TPB * CHUNKS) + threadIdx.x;

    float4 v[CHUNKS];
    #pragma unroll
    for (int k = 0; k < CHUNKS; k++)
        v[k] = __ldcs(&x[base + k * TPB]);

    rope_math(v, base & 15, dparam, thetas);

    #pragma unroll
    for (int k = 0; k < CHUNKS; k++)
        __stcs(&out[base + k * TPB], v[k]);
}

// Guarded fallback (not taken for the bench shape).
__global__ __launch_bounds__(TPB) void rope8_guarded(
    const float4* __restrict__ x,
    const float*  __restrict__ dparam,
    const float*  __restrict__ thetas,
    float4*       __restrict__ out,
    int n4)
{
    int base = blockIdx.x * (TPB * CHUNKS) + threadIdx.x;

    float4 v[CHUNKS];
    #pragma unroll
    for (int k = 0; k < CHUNKS; k++) {
        int i = base + k * TPB;
        if (i < n4) v[k] = __ldcs(&x[i]);
    }

    rope_math(v, base & 15, dparam, thetas);

    #pragma unroll
    for (int k = 0; k < CHUNKS; k++) {
        int i = base + k * TPB;
        if (i < n4) __stcs(&out[i], v[k]);
    }
}

extern "C" void kernel_launch(void* const* d_in, const int* in_sizes, int n_in,
                              void* d_out, int out_size)
{
    const float4* x      = (const float4*)d_in[0];
    const float*  dparam = (const float*)d_in[1];
    const float*  thetas = (const float*)d_in[2];
    float4*       out    = (float4*)d_out;

    int n4 = in_sizes[0] / 4;                   // 8,388,608 float4 chunks
    const int per_block = TPB * CHUNKS;         // 2048
    if (n4 % per_block == 0) {
        rope8_exact<<<n4 / per_block, TPB>>>(x, dparam, thetas, out);
    } else {
        int blocks = (n4 + per_block - 1) / per_block;
        rope8_guarded<<<blocks, TPB>>>(x, dparam, thetas, out, n4);
    }
}